// round 14
// baseline (speedup 1.0000x reference)
#include <cuda_runtime.h>
#include <cuda_fp16.h>
#include <cstdint>

#define NB   64
#define ND   2048
#define NE   64
#define NH1  512
#define NH2  256
#define EPSB 1e-5f

// Scratch (allocation-free)
__device__ __align__(16) uint32_t g_WF[ND * NH1];  // word 2p={F2}, 2p+1={W1c2} per h-pair (4 MB)
__device__ float g_Gp[4 * NB * NH1];
__device__ float g_G[NB * NH1];                // ((rep@W1d)+b1)*c1 + c0
__device__ float g_c1[NH1], g_c0[NH1];
__device__ float g_e1[NH2], g_e0[NH2], g_w3[NH2];
__device__ __half g_W2t[NH2 * NH1];            // W2^T fp16  [o][h]

// ===================== helpers =====================
__device__ __forceinline__ uint32_t smem_u32(const void* p) {
    uint32_t a;
    asm("{ .reg .u64 t; cvta.to.shared.u64 t, %1; cvt.u32.u64 %0, t; }" : "=r"(a) : "l"(p));
    return a;
}
__device__ __forceinline__ void ldsm_x4(uint32_t* r, uint32_t addr) {
    asm volatile("ldmatrix.sync.aligned.m8n8.x4.shared.b16 {%0,%1,%2,%3}, [%4];"
                 : "=r"(r[0]), "=r"(r[1]), "=r"(r[2]), "=r"(r[3]) : "r"(addr));
}
__device__ __forceinline__ void mma_f16(float* d, const uint32_t* a, const uint32_t* b) {
    asm volatile("mma.sync.aligned.m16n8k16.row.col.f32.f16.f16.f32 "
                 "{%0,%1,%2,%3}, {%4,%5,%6,%7}, {%8,%9}, {%0,%1,%2,%3};"
                 : "+f"(d[0]), "+f"(d[1]), "+f"(d[2]), "+f"(d[3])
                 : "r"(a[0]), "r"(a[1]), "r"(a[2]), "r"(a[3]), "r"(b[0]), "r"(b[1]));
}
__device__ __forceinline__ void cpasync16(uint32_t dst, const void* src) {
    asm volatile("cp.async.cg.shared.global [%0], [%1], 16;"
                 :: "r"(dst), "l"(__cvta_generic_to_global(src)) : "memory");
}
#define CP_COMMIT() asm volatile("cp.async.commit_group;" ::: "memory")
#define CP_WAIT0()  asm volatile("cp.async.wait_group 0;" ::: "memory")
#define SWZ(x) ((x) ^ (((x) >> 3) & 0x70))

__device__ __forceinline__ __half2 u32_h2(uint32_t v) { return *(__half2*)&v; }
__device__ __forceinline__ uint32_t h2_u32(__half2 v) { return *(uint32_t*)&v; }
__device__ __forceinline__ uint32_t pack_h2(float a, float b) {
    __half2 h = __floats2half2_rn(a, b);
    return *(uint32_t*)&h;
}

// ===================== prep kernels (3 launches before main) =====================
__global__ void prep_consts(const float* __restrict__ g1, const float* __restrict__ beta1,
                            const float* __restrict__ m1, const float* __restrict__ v1,
                            const float* __restrict__ b2, const float* __restrict__ g2,
                            const float* __restrict__ beta2, const float* __restrict__ m2,
                            const float* __restrict__ v2, const float* __restrict__ W3) {
    int t = threadIdx.x;
    if (t < NH1) {
        float c1 = g1[t] * rsqrtf(v1[t] + EPSB);
        g_c1[t] = c1;
        g_c0[t] = beta1[t] - m1[t] * c1;
    }
    if (t < NH2) {
        float e1 = g2[t] * rsqrtf(v2[t] + EPSB);
        g_e1[t] = e1;
        g_e0[t] = (b2[t] - m2[t]) * e1 + beta2[t];
        g_w3[t] = W3[t];
    }
}

__global__ __launch_bounds__(512) void mega_prep(const float* __restrict__ rep,
                                                 const float* __restrict__ emb,
                                                 const float* __restrict__ W1,
                                                 const float* __restrict__ W2) {
    __shared__ float sh[2 * 512];
    const int cb = blockIdx.x;
    const int t  = threadIdx.x;
    if (cb < 256) {
        int kb = cb * 8;
        for (int i = t; i < 8 * NE; i += 512) sh[i] = emb[(size_t)kb * NE + i];
        __syncthreads();
        const float* W1e = W1 + (size_t)ND * NH1;
        float acc[8];
#pragma unroll
        for (int kr = 0; kr < 8; kr++) acc[kr] = 0.f;
#pragma unroll 4
        for (int e = 0; e < NE; e++) {
            float w = W1e[(size_t)e * NH1 + t];
#pragma unroll
            for (int kr = 0; kr < 8; kr++) acc[kr] = fmaf(sh[kr * NE + e], w, acc[kr]);
        }
        float c1h = g_c1[t];
#pragma unroll
        for (int kr = 0; kr < 8; kr++) {
            int k = kb + kr;
            float F  = acc[kr] * c1h;
            float Wc = W1[(size_t)k * NH1 + t] * c1h;
            float Fn = __shfl_down_sync(0xffffffffu, F, 1);
            float Wn = __shfl_down_sync(0xffffffffu, Wc, 1);
            if (!(t & 1)) {
                uint2 v;
                v.x = pack_h2(F, Fn);
                v.y = pack_h2(Wc, Wn);
                *(uint2*)(g_WF + (size_t)k * NH1 + t) = v;
            }
        }
    } else if (cb < 384) {
        int idx = cb - 256;
        int b0  = (idx & 31) * 2;
        int d0  = (idx >> 5) * 512;
        sh[t]       = rep[(size_t)b0 * ND + d0 + t];
        sh[512 + t] = rep[(size_t)(b0 + 1) * ND + d0 + t];
        __syncthreads();
        float a0 = 0.f, a1 = 0.f;
        const float* Wp = W1 + (size_t)d0 * NH1 + t;
#pragma unroll 8
        for (int d = 0; d < 512; d++) {
            float w = Wp[(size_t)d * NH1];
            a0 = fmaf(sh[d], w, a0);
            a1 = fmaf(sh[512 + d], w, a1);
        }
        g_Gp[((size_t)(idx >> 5) * NB + b0) * NH1 + t]     = a0;
        g_Gp[((size_t)(idx >> 5) * NB + b0 + 1) * NH1 + t] = a1;
    } else {
        int idx = cb - 384;
        int h0 = (idx & 15) * 32, o0 = (idx >> 4) * 32;
        int tx = t & 31, ty = t >> 5;
#pragma unroll
        for (int r = 0; r < 2; r++) {
            int row = ty + 16 * r;
            float v = W2[(size_t)(h0 + tx) * NH2 + o0 + row];
            g_W2t[(size_t)(o0 + row) * NH1 + h0 + tx] = __float2half_rn(v);
        }
    }
}

__global__ __launch_bounds__(512) void prep_G_fold(const float* __restrict__ b1) {
    const int b = blockIdx.x;
    const int h = threadIdx.x;
    float s = g_Gp[((size_t)0 * NB + b) * NH1 + h]
            + g_Gp[((size_t)1 * NB + b) * NH1 + h]
            + g_Gp[((size_t)2 * NB + b) * NH1 + h]
            + g_Gp[((size_t)3 * NB + b) * NH1 + h];
    g_G[(size_t)b * NH1 + h] = fmaf(s + b1[h], g_c1[h], g_c0[h]);
}

// ===================== main HMMA kernel (fp16, 64x64 warp tiles) =====================
// Grid: (ND/128, NB). 256 threads (8 warps). CTA: 128 rows x 256 cols, K=512 in 8 chunks.
// Warp tile 64x64 (2x4 warp grid): 1.0 smem-wavefront per MMA.
// A double-buffered 2x16KB, B double-buffered 2x32KB. 1 CTA/SM (regs ~190).
#define SM_E1      0          // 256 f
#define SM_E0      1024
#define SM_W3      2048
#define SM_G       3072       // 512 half -> 1KB
#define SM_REPS    4096       // 128 f -> 512B
#define SM_PART    4608       // 512 f -> 2KB -> 6656
#define SM_A       8192       // 2 x 16KB
#define A_STRIDE   16384
#define SM_B       40960      // 2 x 32KB
#define B_STRIDE   32768
#define SM_TOTAL   106496

__global__ __launch_bounds__(256, 1) void fused_mma(
    const float* __restrict__ rep, const float* __restrict__ b3,
    float* __restrict__ out)
{
    extern __shared__ __align__(1024) char smem[];
    const uint32_t sb = smem_u32(smem);
    const int b  = blockIdx.y;
    const int k0 = blockIdx.x * 128;
    const int t  = threadIdx.x;
    const int wid = t >> 5, lane = t & 31;
    const int rowg = wid >> 2, colg = wid & 3;   // 2 x 4 warp grid

    // stage constants
    if (t < 256) {
        *(float*)(smem + SM_E1 + t * 4) = g_e1[t];
        *(float*)(smem + SM_E0 + t * 4) = g_e0[t];
        *(float*)(smem + SM_W3 + t * 4) = g_w3[t];
    }
    *(__half*)(smem + SM_G + t * 2)         = __float2half_rn(g_G[(size_t)b * NH1 + t]);
    *(__half*)(smem + SM_G + (t + 256) * 2) = __float2half_rn(g_G[(size_t)b * NH1 + t + 256]);
    if (t < 128) *(float*)(smem + SM_REPS + t * 4) = rep[(size_t)b * ND + k0 + t];
    __syncthreads();

    // B load: chunk ch (64 h, fp16, 256 o-rows) into buffer ch&1
    auto loadB = [&](int ch) {
        const int h0 = ch * 64;
        uint32_t bufB = sb + SM_B + (ch & 1) * B_STRIDE;
#pragma unroll
        for (int i = 0; i < 4; i++) {
            int idx = t + i * 256;              // 0..1023
            int row = idx >> 2, seg = idx & 3;
            cpasync16(bufB + SWZ(row * 128 + seg * 16),
                      g_W2t + (size_t)row * NH1 + h0 + seg * 8);
        }
#pragma unroll
        for (int i = 0; i < 4; i++) {
            int idx = t + i * 256;
            int row = idx >> 2, seg = (idx & 3) + 4;
            cpasync16(bufB + SWZ(row * 128 + seg * 16),
                      g_W2t + (size_t)row * NH1 + h0 + seg * 8);
        }
        CP_COMMIT();
    };

    const int krow = t >> 1;          // 0..127 (2 threads per row)
    const int hb   = (t & 1) * 32;    // 32 h per thread
    const float rp = *(const float*)(smem + SM_REPS + krow * 4);
    const __half2 nrp2  = __float2half2_rn(-rp);
    const __half2 zero2 = __float2half2_rn(0.f);

    // A build: chunk ch into A buffer ch&1 (fp16, 128 rows x 64 h, SW128)
    auto buildA = [&](int ch) {
        const int h0 = ch * 64;
#pragma unroll
        for (int j = 0; j < 4; j++) {           // 4 groups of 8 h
            int h8 = hb + j * 8;
            const uint32_t* wp = g_WF + (size_t)(k0 + krow) * NH1 + h0 + h8;
            uint4 wf0 = *(const uint4*)wp;        // h8..h8+3: {F2,W2,F2,W2}
            uint4 wf1 = *(const uint4*)(wp + 4);  // h8+4..h8+7
            uint4 gq = *(const uint4*)(smem + SM_G + (h0 + h8) * 2);  // 4 half2
            __half2 u0 = __hfma2(nrp2, u32_h2(wf0.y), __hadd2(u32_h2(gq.x), u32_h2(wf0.x)));
            __half2 u1 = __hfma2(nrp2, u32_h2(wf0.w), __hadd2(u32_h2(gq.y), u32_h2(wf0.z)));
            __half2 u2 = __hfma2(nrp2, u32_h2(wf1.y), __hadd2(u32_h2(gq.z), u32_h2(wf1.x)));
            __half2 u3 = __hfma2(nrp2, u32_h2(wf1.w), __hadd2(u32_h2(gq.w), u32_h2(wf1.z)));
            uint4 hv;
            hv.x = h2_u32(__hmax2(u0, zero2));
            hv.y = h2_u32(__hmax2(u1, zero2));
            hv.z = h2_u32(__hmax2(u2, zero2));
            hv.w = h2_u32(__hmax2(u3, zero2));
            uint32_t boff = SWZ(krow * 128 + h8 * 2);
            *(uint4*)(smem + SM_A + (ch & 1) * A_STRIDE + boff) = hv;
        }
    };

    // ldmatrix address precompute
    uint32_t aOff[4]; int aX[4];
#pragma unroll
    for (int mt = 0; mt < 4; mt++) {
        int rowA = rowg * 64 + mt * 16 + (lane & 15);
        aOff[mt] = rowA * 128;
        aX[mt]   = (rowA & 7) << 4;
    }
    const int aCol = lane & 16;
    int bRow[4], bX[4];
#pragma unroll
    for (int bt = 0; bt < 4; bt++) {
        int rowB = colg * 64 + bt * 16 + (lane & 7) + ((lane & 16) >> 1);
        bRow[bt] = rowB * 128;
        bX[bt]   = (rowB & 7) << 4;
    }
    const int bCol = (lane & 8) << 1;

    float D[4][8][4];
#pragma unroll
    for (int mt = 0; mt < 4; mt++)
#pragma unroll
        for (int nt = 0; nt < 8; nt++)
#pragma unroll
            for (int j = 0; j < 4; j++) D[mt][nt][j] = 0.f;

    // prologue
    loadB(0);
    buildA(0);
    CP_WAIT0();
    __syncthreads();

#pragma unroll 1
    for (int ch = 0; ch < 8; ch++) {
        if (ch < 7) loadB(ch + 1);               // async into other B buffer
        const uint32_t bufA = sb + SM_A + (ch & 1) * A_STRIDE;
        const uint32_t bufB = sb + SM_B + (ch & 1) * B_STRIDE;
        // ---- MMA(ch): 4 k-steps of 16; 32 MMAs per k-step ----
#pragma unroll
        for (int ks = 0; ks < 4; ks++) {
            const int cA = ks * 32 + aCol;
            const int cB = ks * 32 + bCol;
            uint32_t ah[4][4], bh[4][4];
#pragma unroll
            for (int mt = 0; mt < 4; mt++)
                ldsm_x4(ah[mt], bufA + aOff[mt] + (cA ^ aX[mt]));
#pragma unroll
            for (int bt = 0; bt < 4; bt++)
                ldsm_x4(bh[bt], bufB + bRow[bt] + (cB ^ bX[bt]));
#pragma unroll
            for (int mt = 0; mt < 4; mt++)
#pragma unroll
                for (int bt = 0; bt < 4; bt++) {
                    mma_f16(D[mt][2 * bt],     ah[mt], bh[bt]);
                    mma_f16(D[mt][2 * bt + 1], ah[mt], bh[bt] + 2);
                }
        }
        if (ch < 7) buildA(ch + 1);              // other A buffer; overlaps B arrival
        CP_WAIT0();
        __syncthreads();
    }

    // ---- epilogue: BN2 + relu + W3 dot, reduce over o ----
#pragma unroll
    for (int mt = 0; mt < 4; mt++) {
        int r = rowg * 64 + mt * 16 + (lane >> 2);
        float s0 = 0.f, s1 = 0.f;
#pragma unroll
        for (int nt = 0; nt < 8; nt++) {
#pragma unroll
            for (int j = 0; j < 2; j++) {
                int o = colg * 64 + nt * 8 + 2 * (lane & 3) + j;
                float e1 = *(const float*)(smem + SM_E1 + o * 4);
                float e0 = *(const float*)(smem + SM_E0 + o * 4);
                float w3 = *(const float*)(smem + SM_W3 + o * 4);
                s0 = fmaf(fmaxf(fmaf(D[mt][nt][j],     e1, e0), 0.f), w3, s0);
                s1 = fmaf(fmaxf(fmaf(D[mt][nt][2 + j], e1, e0), 0.f), w3, s1);
            }
        }
        s0 += __shfl_xor_sync(0xffffffffu, s0, 1);
        s0 += __shfl_xor_sync(0xffffffffu, s0, 2);
        s1 += __shfl_xor_sync(0xffffffffu, s1, 1);
        s1 += __shfl_xor_sync(0xffffffffu, s1, 2);
        if ((lane & 3) == 0) {
            *(float*)(smem + SM_PART + (colg * 128 + r) * 4)     = s0;
            *(float*)(smem + SM_PART + (colg * 128 + r + 8) * 4) = s1;
        }
    }
    __syncthreads();
    if (t < 128) {
        float v = *(const float*)(smem + SM_PART + t * 4)
                + *(const float*)(smem + SM_PART + (128 + t) * 4)
                + *(const float*)(smem + SM_PART + (256 + t) * 4)
                + *(const float*)(smem + SM_PART + (384 + t) * 4);
        out[(size_t)b * ND + k0 + t] = v + b3[0];
    }
}

extern "C" void kernel_launch(void* const* d_in, const int* in_sizes, int n_in,
                              void* d_out, int out_size) {
    const float* rep   = (const float*)d_in[0];
    const float* emb   = (const float*)d_in[1];
    const float* W1    = (const float*)d_in[2];
    const float* b1    = (const float*)d_in[3];
    const float* g1    = (const float*)d_in[4];
    const float* beta1 = (const float*)d_in[5];
    const float* m1    = (const float*)d_in[6];
    const float* v1    = (const float*)d_in[7];
    const float* W2    = (const float*)d_in[8];
    const float* b2    = (const float*)d_in[9];
    const float* g2    = (const float*)d_in[10];
    const float* beta2 = (const float*)d_in[11];
    const float* m2    = (const float*)d_in[12];
    const float* v2    = (const float*)d_in[13];
    const float* W3    = (const float*)d_in[14];
    const float* b3    = (const float*)d_in[15];
    float* out = (float*)d_out;

    cudaFuncSetAttribute(fused_mma, cudaFuncAttributeMaxDynamicSharedMemorySize, SM_TOTAL);

    prep_consts<<<1, 512>>>(g1, beta1, m1, v1, b2, g2, beta2, m2, v2, W3);   // 0
    mega_prep<<<512, 512>>>(rep, emb, W1, W2);                               // 1
    prep_G_fold<<<NB, 512>>>(b1);                                            // 2
    dim3 grid(ND / 128, NB);
    fused_mma<<<grid, 256, SM_TOTAL>>>(rep, b3, out);                        // 3 (profiled)
}

// round 15
// speedup vs baseline: 2.0955x; 2.0955x over previous
#include <cuda_runtime.h>
#include <cuda_fp16.h>
#include <cstdint>

#define NB   64
#define ND   2048
#define NE   64
#define NH1  512
#define NH2  256
#define EPSB 1e-5f

// Scratch (allocation-free)
__device__ __align__(16) uint32_t g_WF[ND * NH1];  // word 2p={F2}, 2p+1={W1c2} per h-pair (4 MB)
__device__ float g_Gp[4 * NB * NH1];
__device__ float g_G[NB * NH1];                // ((rep@W1d)+b1)*c1 + c0
__device__ float g_c1[NH1], g_c0[NH1];
__device__ float g_e1[NH2], g_e0[NH2], g_w3[NH2];
__device__ __half g_W2t[NH2 * NH1];            // W2^T fp16  [o][h]

// ===================== helpers =====================
__device__ __forceinline__ uint32_t smem_u32(const void* p) {
    uint32_t a;
    asm("{ .reg .u64 t; cvta.to.shared.u64 t, %1; cvt.u32.u64 %0, t; }" : "=r"(a) : "l"(p));
    return a;
}
__device__ __forceinline__ void ldsm_x4(uint32_t* r, uint32_t addr) {
    asm volatile("ldmatrix.sync.aligned.m8n8.x4.shared.b16 {%0,%1,%2,%3}, [%4];"
                 : "=r"(r[0]), "=r"(r[1]), "=r"(r[2]), "=r"(r[3]) : "r"(addr));
}
__device__ __forceinline__ void mma_f16(float* d, const uint32_t* a, const uint32_t* b) {
    asm volatile("mma.sync.aligned.m16n8k16.row.col.f32.f16.f16.f32 "
                 "{%0,%1,%2,%3}, {%4,%5,%6,%7}, {%8,%9}, {%0,%1,%2,%3};"
                 : "+f"(d[0]), "+f"(d[1]), "+f"(d[2]), "+f"(d[3])
                 : "r"(a[0]), "r"(a[1]), "r"(a[2]), "r"(a[3]), "r"(b[0]), "r"(b[1]));
}
__device__ __forceinline__ void cpasync16(uint32_t dst, const void* src) {
    asm volatile("cp.async.cg.shared.global [%0], [%1], 16;"
                 :: "r"(dst), "l"(__cvta_generic_to_global(src)) : "memory");
}
#define CP_COMMIT() asm volatile("cp.async.commit_group;" ::: "memory")
#define CP_WAIT0()  asm volatile("cp.async.wait_group 0;" ::: "memory")
#define SWZ(x) ((x) ^ (((x) >> 3) & 0x70))

__device__ __forceinline__ __half2 u32_h2(uint32_t v) { return *(__half2*)&v; }
__device__ __forceinline__ uint32_t h2_u32(__half2 v) { return *(uint32_t*)&v; }
__device__ __forceinline__ uint32_t pack_h2(float a, float b) {
    __half2 h = __floats2half2_rn(a, b);
    return *(uint32_t*)&h;
}

// ===================== prep kernels (3 launches before main) =====================
__global__ void prep_consts(const float* __restrict__ g1, const float* __restrict__ beta1,
                            const float* __restrict__ m1, const float* __restrict__ v1,
                            const float* __restrict__ b2, const float* __restrict__ g2,
                            const float* __restrict__ beta2, const float* __restrict__ m2,
                            const float* __restrict__ v2, const float* __restrict__ W3) {
    int t = threadIdx.x;
    if (t < NH1) {
        float c1 = g1[t] * rsqrtf(v1[t] + EPSB);
        g_c1[t] = c1;
        g_c0[t] = beta1[t] - m1[t] * c1;
    }
    if (t < NH2) {
        float e1 = g2[t] * rsqrtf(v2[t] + EPSB);
        g_e1[t] = e1;
        g_e0[t] = (b2[t] - m2[t]) * e1 + beta2[t];
        g_w3[t] = W3[t];
    }
}

__global__ __launch_bounds__(512) void mega_prep(const float* __restrict__ rep,
                                                 const float* __restrict__ emb,
                                                 const float* __restrict__ W1,
                                                 const float* __restrict__ W2) {
    __shared__ float sh[2 * 512];
    const int cb = blockIdx.x;
    const int t  = threadIdx.x;
    if (cb < 256) {
        int kb = cb * 8;
        for (int i = t; i < 8 * NE; i += 512) sh[i] = emb[(size_t)kb * NE + i];
        __syncthreads();
        const float* W1e = W1 + (size_t)ND * NH1;
        float acc[8];
#pragma unroll
        for (int kr = 0; kr < 8; kr++) acc[kr] = 0.f;
#pragma unroll 4
        for (int e = 0; e < NE; e++) {
            float w = W1e[(size_t)e * NH1 + t];
#pragma unroll
            for (int kr = 0; kr < 8; kr++) acc[kr] = fmaf(sh[kr * NE + e], w, acc[kr]);
        }
        float c1h = g_c1[t];
#pragma unroll
        for (int kr = 0; kr < 8; kr++) {
            int k = kb + kr;
            float F  = acc[kr] * c1h;
            float Wc = W1[(size_t)k * NH1 + t] * c1h;
            float Fn = __shfl_down_sync(0xffffffffu, F, 1);
            float Wn = __shfl_down_sync(0xffffffffu, Wc, 1);
            if (!(t & 1)) {
                uint2 v;
                v.x = pack_h2(F, Fn);
                v.y = pack_h2(Wc, Wn);
                *(uint2*)(g_WF + (size_t)k * NH1 + t) = v;
            }
        }
    } else if (cb < 384) {
        int idx = cb - 256;
        int b0  = (idx & 31) * 2;
        int d0  = (idx >> 5) * 512;
        sh[t]       = rep[(size_t)b0 * ND + d0 + t];
        sh[512 + t] = rep[(size_t)(b0 + 1) * ND + d0 + t];
        __syncthreads();
        float a0 = 0.f, a1 = 0.f;
        const float* Wp = W1 + (size_t)d0 * NH1 + t;
#pragma unroll 8
        for (int d = 0; d < 512; d++) {
            float w = Wp[(size_t)d * NH1];
            a0 = fmaf(sh[d], w, a0);
            a1 = fmaf(sh[512 + d], w, a1);
        }
        g_Gp[((size_t)(idx >> 5) * NB + b0) * NH1 + t]     = a0;
        g_Gp[((size_t)(idx >> 5) * NB + b0 + 1) * NH1 + t] = a1;
    } else {
        int idx = cb - 384;
        int h0 = (idx & 15) * 32, o0 = (idx >> 4) * 32;
        int tx = t & 31, ty = t >> 5;
#pragma unroll
        for (int r = 0; r < 2; r++) {
            int row = ty + 16 * r;
            float v = W2[(size_t)(h0 + tx) * NH2 + o0 + row];
            g_W2t[(size_t)(o0 + row) * NH1 + h0 + tx] = __float2half_rn(v);
        }
    }
}

__global__ __launch_bounds__(512) void prep_G_fold(const float* __restrict__ b1) {
    const int b = blockIdx.x;
    const int h = threadIdx.x;
    float s = g_Gp[((size_t)0 * NB + b) * NH1 + h]
            + g_Gp[((size_t)1 * NB + b) * NH1 + h]
            + g_Gp[((size_t)2 * NB + b) * NH1 + h]
            + g_Gp[((size_t)3 * NB + b) * NH1 + h];
    g_G[(size_t)b * NH1 + h] = fmaf(s + b1[h], g_c1[h], g_c0[h]);
}

// ===================== main HMMA kernel (fp16, 512-thread CTA) =====================
// Grid: (ND/128, NB). 512 threads (16 warps). CTA: 128 rows x 256 cols, K=512 in 8 chunks.
// Warp tile 32x64 (4x4 warp grid). A 2x16KB + B 2x32KB double-buffered. 1 CTA/SM.
// A-build: coalesced (8 lanes x 16B = 128B/row), inputs prefetched to regs pre-MMA.
#define SM_E1      0          // 256 f
#define SM_E0      1024
#define SM_W3      2048
#define SM_G       3072       // 512 half -> 1KB
#define SM_REPS    4096       // 128 f -> 512B
#define SM_PART    4608       // 512 f -> 2KB
#define SM_A       8192       // 2 x 16KB
#define A_STRIDE   16384
#define SM_B       40960      // 2 x 32KB
#define B_STRIDE   32768
#define SM_TOTAL   106496

__global__ __launch_bounds__(512, 1) void fused_mma(
    const float* __restrict__ rep, const float* __restrict__ b3,
    float* __restrict__ out)
{
    extern __shared__ __align__(1024) char smem[];
    const uint32_t sb = smem_u32(smem);
    const int b  = blockIdx.y;
    const int k0 = blockIdx.x * 128;
    const int t  = threadIdx.x;
    const int wid = t >> 5, lane = t & 31;
    const int rowg = wid >> 2, colg = wid & 3;   // 4 x 4 warp grid, 32x64 tiles

    // stage constants
    if (t < 256) {
        *(float*)(smem + SM_E1 + t * 4) = g_e1[t];
        *(float*)(smem + SM_E0 + t * 4) = g_e0[t];
        *(float*)(smem + SM_W3 + t * 4) = g_w3[t];
        *(__half*)(smem + SM_G + t * 2)         = __float2half_rn(g_G[(size_t)b * NH1 + t]);
        *(__half*)(smem + SM_G + (t + 256) * 2) = __float2half_rn(g_G[(size_t)b * NH1 + t + 256]);
    }
    if (t < 128) *(float*)(smem + SM_REPS + t * 4) = rep[(size_t)b * ND + k0 + t];
    __syncthreads();

    // B load: chunk ch (256 o-rows x 64 h fp16 = 32KB) into buffer ch&1
    auto loadB = [&](int ch) {
        const int h0 = ch * 64;
        uint32_t bufB = sb + SM_B + (ch & 1) * B_STRIDE;
#pragma unroll
        for (int i = 0; i < 4; i++) {
            int idx = t + i * 512;              // 0..2047
            int row = idx >> 3, seg = idx & 7;
            cpasync16(bufB + SWZ(row * 128 + seg * 16),
                      g_W2t + (size_t)row * NH1 + h0 + seg * 8);
        }
        CP_COMMIT();
    };

    // A build layout: seg s = t&7 (16B in-row), rows r0 = t>>3, r1 = 64 + (t>>3).
    // Each thread: 2 rows x 8 h (two groups of 4h: h=4s.. and h=32+4s..).
    const int s    = t & 7;
    const int rl   = t >> 3;          // 0..63
    const float rp0 = *(const float*)(smem + SM_REPS + rl * 4);
    const float rp1 = *(const float*)(smem + SM_REPS + (64 + rl) * 4);
    const __half2 nrp0 = __float2half2_rn(-rp0);
    const __half2 nrp1 = __float2half2_rn(-rp1);
    const __half2 zero2 = __float2half2_rn(0.f);

    uint4 pf[4];   // prefetched inputs: [row0 grp0, row0 grp1, row1 grp0, row1 grp1]
    auto prefetchA = [&](int ch) {
        const int h0 = ch * 64;
        const uint32_t* base0 = g_WF + (size_t)(k0 + rl) * NH1 + h0;
        const uint32_t* base1 = g_WF + (size_t)(k0 + 64 + rl) * NH1 + h0;
        pf[0] = *(const uint4*)(base0 + 4 * s);         // h = 4s..4s+3 (F2,W2,F2,W2)
        pf[1] = *(const uint4*)(base0 + 32 + 4 * s);    // h = 32+4s..
        pf[2] = *(const uint4*)(base1 + 4 * s);
        pf[3] = *(const uint4*)(base1 + 32 + 4 * s);
    };
    auto storeA = [&](int ch) {
        const int h0 = ch * 64;
        uint32_t bufA = sb + SM_A + (ch & 1) * A_STRIDE;
#pragma unroll
        for (int pr = 0; pr < 2; pr++) {        // row group
            int row = pr * 64 + rl;
            __half2 nrp = pr ? nrp1 : nrp0;
#pragma unroll
            for (int g = 0; g < 2; g++) {       // h group
                uint4 wf = pf[pr * 2 + g];
                int h4 = g * 32 + 4 * s;
                __half2 G0 = *(const __half2*)(smem + SM_G + (h0 + h4) * 2);
                __half2 G1 = *(const __half2*)(smem + SM_G + (h0 + h4 + 2) * 2);
                __half2 u0 = __hfma2(nrp, u32_h2(wf.y), __hadd2(G0, u32_h2(wf.x)));
                __half2 u1 = __hfma2(nrp, u32_h2(wf.w), __hadd2(G1, u32_h2(wf.z)));
                uint2 hv;
                hv.x = h2_u32(__hmax2(u0, zero2));
                hv.y = h2_u32(__hmax2(u1, zero2));
                *(uint2*)(smem + SM_A + (ch & 1) * A_STRIDE +
                          SWZ(row * 128 + h4 * 2)) = hv;
            }
        }
    };

    // ldmatrix address precompute
    uint32_t aOff[2]; int aX[2];
#pragma unroll
    for (int mt = 0; mt < 2; mt++) {
        int rowA = rowg * 32 + mt * 16 + (lane & 15);
        aOff[mt] = rowA * 128;
        aX[mt]   = (rowA & 7) << 4;
    }
    const int aCol = lane & 16;
    int bRow[4], bX[4];
#pragma unroll
    for (int bt = 0; bt < 4; bt++) {
        int rowB = colg * 64 + bt * 16 + (lane & 7) + ((lane & 16) >> 1);
        bRow[bt] = rowB * 128;
        bX[bt]   = (rowB & 7) << 4;
    }
    const int bCol = (lane & 8) << 1;

    float D[2][8][4];
#pragma unroll
    for (int mt = 0; mt < 2; mt++)
#pragma unroll
        for (int nt = 0; nt < 8; nt++)
#pragma unroll
            for (int j = 0; j < 4; j++) D[mt][nt][j] = 0.f;

    // prologue
    loadB(0);
    prefetchA(0);
    storeA(0);
    CP_WAIT0();
    __syncthreads();

#pragma unroll 1
    for (int ch = 0; ch < 8; ch++) {
        if (ch < 7) {
            prefetchA(ch + 1);                   // LDG latency hides under MMA below
            loadB(ch + 1);                       // async into other B buffer
        }
        const uint32_t bufA = sb + SM_A + (ch & 1) * A_STRIDE;
        const uint32_t bufB = sb + SM_B + (ch & 1) * B_STRIDE;
        // ---- MMA(ch): 4 k-steps of 16 ----
#pragma unroll
        for (int ks = 0; ks < 4; ks++) {
            const int cA = ks * 32 + aCol;
            const int cB = ks * 32 + bCol;
            uint32_t ah[2][4];
            ldsm_x4(ah[0], bufA + aOff[0] + (cA ^ aX[0]));
            ldsm_x4(ah[1], bufA + aOff[1] + (cA ^ aX[1]));
#pragma unroll
            for (int bth = 0; bth < 2; bth++) {
                uint32_t bh[2][4];
#pragma unroll
                for (int bb = 0; bb < 2; bb++) {
                    int bt = 2 * bth + bb;
                    ldsm_x4(bh[bb], bufB + bRow[bt] + (cB ^ bX[bt]));
                }
#pragma unroll
                for (int mt = 0; mt < 2; mt++)
#pragma unroll
                    for (int bb = 0; bb < 2; bb++) {
                        int nt = 4 * bth + 2 * bb;
                        mma_f16(D[mt][nt],     ah[mt], bh[bb]);
                        mma_f16(D[mt][nt + 1], ah[mt], bh[bb] + 2);
                    }
            }
        }
        if (ch < 7) storeA(ch + 1);              // other A buffer; no race with readers
        CP_WAIT0();
        __syncthreads();
    }

    // ---- epilogue: BN2 + relu + W3 dot, reduce over o ----
#pragma unroll
    for (int mt = 0; mt < 2; mt++) {
        int r = rowg * 32 + mt * 16 + (lane >> 2);
        float s0 = 0.f, s1 = 0.f;
#pragma unroll
        for (int nt = 0; nt < 8; nt++) {
#pragma unroll
            for (int j = 0; j < 2; j++) {
                int o = colg * 64 + nt * 8 + 2 * (lane & 3) + j;
                float e1 = *(const float*)(smem + SM_E1 + o * 4);
                float e0 = *(const float*)(smem + SM_E0 + o * 4);
                float w3 = *(const float*)(smem + SM_W3 + o * 4);
                s0 = fmaf(fmaxf(fmaf(D[mt][nt][j],     e1, e0), 0.f), w3, s0);
                s1 = fmaf(fmaxf(fmaf(D[mt][nt][2 + j], e1, e0), 0.f), w3, s1);
            }
        }
        s0 += __shfl_xor_sync(0xffffffffu, s0, 1);
        s0 += __shfl_xor_sync(0xffffffffu, s0, 2);
        s1 += __shfl_xor_sync(0xffffffffu, s1, 1);
        s1 += __shfl_xor_sync(0xffffffffu, s1, 2);
        if ((lane & 3) == 0) {
            *(float*)(smem + SM_PART + (colg * 128 + r) * 4)     = s0;
            *(float*)(smem + SM_PART + (colg * 128 + r + 8) * 4) = s1;
        }
    }
    __syncthreads();
    if (t < 128) {
        float v = *(const float*)(smem + SM_PART + t * 4)
                + *(const float*)(smem + SM_PART + (128 + t) * 4)
                + *(const float*)(smem + SM_PART + (256 + t) * 4)
                + *(const float*)(smem + SM_PART + (384 + t) * 4);
        out[(size_t)b * ND + k0 + t] = v + b3[0];
    }
}

extern "C" void kernel_launch(void* const* d_in, const int* in_sizes, int n_in,
                              void* d_out, int out_size) {
    const float* rep   = (const float*)d_in[0];
    const float* emb   = (const float*)d_in[1];
    const float* W1    = (const float*)d_in[2];
    const float* b1    = (const float*)d_in[3];
    const float* g1    = (const float*)d_in[4];
    const float* beta1 = (const float*)d_in[5];
    const float* m1    = (const float*)d_in[6];
    const float* v1    = (const float*)d_in[7];
    const float* W2    = (const float*)d_in[8];
    const float* b2    = (const float*)d_in[9];
    const float* g2    = (const float*)d_in[10];
    const float* beta2 = (const float*)d_in[11];
    const float* m2    = (const float*)d_in[12];
    const float* v2    = (const float*)d_in[13];
    const float* W3    = (const float*)d_in[14];
    const float* b3    = (const float*)d_in[15];
    float* out = (float*)d_out;

    cudaFuncSetAttribute(fused_mma, cudaFuncAttributeMaxDynamicSharedMemorySize, SM_TOTAL);

    prep_consts<<<1, 512>>>(g1, beta1, m1, v1, b2, g2, beta2, m2, v2, W3);   // 0
    mega_prep<<<512, 512>>>(rep, emb, W1, W2);                               // 1
    prep_G_fold<<<NB, 512>>>(b1);                                            // 2
    dim3 grid(ND / 128, NB);
    fused_mma<<<grid, 512, SM_TOTAL>>>(rep, b3, out);                        // 3 (profiled)
}

// round 16
// speedup vs baseline: 2.1277x; 1.0153x over previous
#include <cuda_runtime.h>
#include <cuda_fp16.h>
#include <cstdint>

#define NB   64
#define ND   2048
#define NE   64
#define NH1  512
#define NH2  256
#define EPSB 1e-5f

// Scratch (allocation-free)
__device__ __align__(16) uint32_t g_WF[ND * NH1];  // word 2p={F2}, 2p+1={W1c2} per h-pair (4 MB)
__device__ float g_Gp[4 * NB * NH1];               // split-D partials of rep@W1d
__device__ __half g_W2t[NH2 * NH1];                // W2^T fp16  [o][h]

// ===================== helpers =====================
__device__ __forceinline__ uint32_t smem_u32(const void* p) {
    uint32_t a;
    asm("{ .reg .u64 t; cvta.to.shared.u64 t, %1; cvt.u32.u64 %0, t; }" : "=r"(a) : "l"(p));
    return a;
}
__device__ __forceinline__ void ldsm_x4(uint32_t* r, uint32_t addr) {
    asm volatile("ldmatrix.sync.aligned.m8n8.x4.shared.b16 {%0,%1,%2,%3}, [%4];"
                 : "=r"(r[0]), "=r"(r[1]), "=r"(r[2]), "=r"(r[3]) : "r"(addr));
}
__device__ __forceinline__ void mma_f16(float* d, const uint32_t* a, const uint32_t* b) {
    asm volatile("mma.sync.aligned.m16n8k16.row.col.f32.f16.f16.f32 "
                 "{%0,%1,%2,%3}, {%4,%5,%6,%7}, {%8,%9}, {%0,%1,%2,%3};"
                 : "+f"(d[0]), "+f"(d[1]), "+f"(d[2]), "+f"(d[3])
                 : "r"(a[0]), "r"(a[1]), "r"(a[2]), "r"(a[3]), "r"(b[0]), "r"(b[1]));
}
__device__ __forceinline__ void cpasync16(uint32_t dst, const void* src) {
    asm volatile("cp.async.cg.shared.global [%0], [%1], 16;"
                 :: "r"(dst), "l"(__cvta_generic_to_global(src)) : "memory");
}
#define CP_COMMIT() asm volatile("cp.async.commit_group;" ::: "memory")
#define CP_WAIT0()  asm volatile("cp.async.wait_group 0;" ::: "memory")
#define CP_WAIT1()  asm volatile("cp.async.wait_group 1;" ::: "memory")
#define SWZ(x) ((x) ^ (((x) >> 3) & 0x70))

__device__ __forceinline__ __half2 u32_h2(uint32_t v) { return *(__half2*)&v; }
__device__ __forceinline__ uint32_t h2_u32(__half2 v) { return *(uint32_t*)&v; }
__device__ __forceinline__ uint32_t pack_h2(float a, float b) {
    __half2 h = __floats2half2_rn(a, b);
    return *(uint32_t*)&h;
}

// ===================== mega-prep (single prep launch) =====================
//  [0, 256)   : F = (emb@W1e)*c1 and W1c = W1d*c1, packed fp16 -> g_WF (8 k-rows/CTA)
//  [256, 384) : base partials (b-paired, 4 d-slices)
//  [384, 512) : W2t fp16 transpose
__global__ __launch_bounds__(512) void mega_prep(const float* __restrict__ rep,
                                                 const float* __restrict__ emb,
                                                 const float* __restrict__ W1,
                                                 const float* __restrict__ W2,
                                                 const float* __restrict__ g1,
                                                 const float* __restrict__ v1) {
    __shared__ float sh[2 * 512];
    const int cb = blockIdx.x;
    const int t  = threadIdx.x;
    if (cb < 256) {
        int kb = cb * 8;
        for (int i = t; i < 8 * NE; i += 512) sh[i] = emb[(size_t)kb * NE + i];
        __syncthreads();
        const float* W1e = W1 + (size_t)ND * NH1;
        float acc[8];
#pragma unroll
        for (int kr = 0; kr < 8; kr++) acc[kr] = 0.f;
#pragma unroll 4
        for (int e = 0; e < NE; e++) {
            float w = W1e[(size_t)e * NH1 + t];
#pragma unroll
            for (int kr = 0; kr < 8; kr++) acc[kr] = fmaf(sh[kr * NE + e], w, acc[kr]);
        }
        float c1h = g1[t] * rsqrtf(v1[t] + EPSB);
#pragma unroll
        for (int kr = 0; kr < 8; kr++) {
            int k = kb + kr;
            float F  = acc[kr] * c1h;
            float Wc = W1[(size_t)k * NH1 + t] * c1h;
            float Fn = __shfl_down_sync(0xffffffffu, F, 1);
            float Wn = __shfl_down_sync(0xffffffffu, Wc, 1);
            if (!(t & 1)) {
                uint2 v;
                v.x = pack_h2(F, Fn);
                v.y = pack_h2(Wc, Wn);
                *(uint2*)(g_WF + (size_t)k * NH1 + t) = v;
            }
        }
    } else if (cb < 384) {
        int idx = cb - 256;
        int b0  = (idx & 31) * 2;
        int d0  = (idx >> 5) * 512;
        sh[t]       = rep[(size_t)b0 * ND + d0 + t];
        sh[512 + t] = rep[(size_t)(b0 + 1) * ND + d0 + t];
        __syncthreads();
        float a0 = 0.f, a1 = 0.f;
        const float* Wp = W1 + (size_t)d0 * NH1 + t;
#pragma unroll 8
        for (int d = 0; d < 512; d++) {
            float w = Wp[(size_t)d * NH1];
            a0 = fmaf(sh[d], w, a0);
            a1 = fmaf(sh[512 + d], w, a1);
        }
        g_Gp[((size_t)(idx >> 5) * NB + b0) * NH1 + t]     = a0;
        g_Gp[((size_t)(idx >> 5) * NB + b0 + 1) * NH1 + t] = a1;
    } else {
        int idx = cb - 384;
        int h0 = (idx & 15) * 32, o0 = (idx >> 4) * 32;
        int tx = t & 31, ty = t >> 5;
#pragma unroll
        for (int r = 0; r < 2; r++) {
            int row = ty + 16 * r;
            float v = W2[(size_t)(h0 + tx) * NH2 + o0 + row];
            g_W2t[(size_t)(o0 + row) * NH1 + h0 + tx] = __float2half_rn(v);
        }
    }
}

// ===================== main HMMA kernel =====================
// Grid: (ND/128, NB). 512 threads (16 warps). CTA: 128 rows x 256 cols, K=512 in 8 chunks.
// Warp tile 32x64 (4x4). A 2x16KB double-buffered, B 3x32KB triple-buffered (wait_group 1).
// Prologue computes E1/E0/W3 + G fold in-kernel (no prep_consts / prep_G_fold launches).
#define SM_E1      0          // 256 f
#define SM_E0      1024
#define SM_W3      2048
#define SM_G       3072       // 512 half -> 1KB
#define SM_REPS    4096       // 128 f -> 512B
#define SM_PART    4608       // 512 f -> 2KB
#define SM_A       8192       // 2 x 16KB
#define A_STRIDE   16384
#define SM_B       40960      // 3 x 32KB
#define B_STRIDE   32768
#define SM_TOTAL   139264

__global__ __launch_bounds__(512, 1) void fused_mma(
    const float* __restrict__ rep,
    const float* __restrict__ b1, const float* __restrict__ g1,
    const float* __restrict__ beta1, const float* __restrict__ m1,
    const float* __restrict__ v1,
    const float* __restrict__ b2, const float* __restrict__ g2,
    const float* __restrict__ beta2, const float* __restrict__ m2,
    const float* __restrict__ v2, const float* __restrict__ W3,
    const float* __restrict__ b3, float* __restrict__ out)
{
    extern __shared__ __align__(1024) char smem[];
    const uint32_t sb = smem_u32(smem);
    const int b  = blockIdx.y;
    const int k0 = blockIdx.x * 128;
    const int t  = threadIdx.x;
    const int wid = t >> 5, lane = t & 31;
    const int rowg = wid >> 2, colg = wid & 3;   // 4 x 4 warp grid, 32x64 tiles

    // ---- prologue staging: E consts, G fold, reps ----
    if (t < 256) {
        float e1 = g2[t] * rsqrtf(v2[t] + EPSB);
        *(float*)(smem + SM_E1 + t * 4) = e1;
        *(float*)(smem + SM_E0 + t * 4) = (b2[t] - m2[t]) * e1 + beta2[t];
        *(float*)(smem + SM_W3 + t * 4) = W3[t];
    }
    {
        int h = t;  // 0..511
        float s = g_Gp[((size_t)0 * NB + b) * NH1 + h]
                + g_Gp[((size_t)1 * NB + b) * NH1 + h]
                + g_Gp[((size_t)2 * NB + b) * NH1 + h]
                + g_Gp[((size_t)3 * NB + b) * NH1 + h];
        float c1 = g1[h] * rsqrtf(v1[h] + EPSB);
        float c0 = beta1[h] - m1[h] * c1;
        float G  = fmaf(s + b1[h], c1, c0);
        *(__half*)(smem + SM_G + h * 2) = __float2half_rn(G);
    }
    if (t < 128) *(float*)(smem + SM_REPS + t * 4) = rep[(size_t)b * ND + k0 + t];
    __syncthreads();

    // B load: chunk ch (256 o-rows x 64 h fp16 = 32KB) into buffer ch%3
    auto loadB = [&](int ch) {
        const int h0 = ch * 64;
        uint32_t bufB = sb + SM_B + (ch % 3) * B_STRIDE;
#pragma unroll
        for (int i = 0; i < 4; i++) {
            int idx = t + i * 512;              // 0..2047
            int row = idx >> 3, seg = idx & 7;
            cpasync16(bufB + SWZ(row * 128 + seg * 16),
                      g_W2t + (size_t)row * NH1 + h0 + seg * 8);
        }
        CP_COMMIT();
    };

    // A build: seg s = t&7 (16B in-row), rows rl and 64+rl
    const int s    = t & 7;
    const int rl   = t >> 3;          // 0..63
    const float rp0 = *(const float*)(smem + SM_REPS + rl * 4);
    const float rp1 = *(const float*)(smem + SM_REPS + (64 + rl) * 4);
    const __half2 nrp0 = __float2half2_rn(-rp0);
    const __half2 nrp1 = __float2half2_rn(-rp1);
    const __half2 zero2 = __float2half2_rn(0.f);

    uint4 pf[4];   // prefetched inputs
    auto prefetchA = [&](int ch) {
        const int h0 = ch * 64;
        const uint32_t* base0 = g_WF + (size_t)(k0 + rl) * NH1 + h0;
        const uint32_t* base1 = g_WF + (size_t)(k0 + 64 + rl) * NH1 + h0;
        pf[0] = *(const uint4*)(base0 + 4 * s);
        pf[1] = *(const uint4*)(base0 + 32 + 4 * s);
        pf[2] = *(const uint4*)(base1 + 4 * s);
        pf[3] = *(const uint4*)(base1 + 32 + 4 * s);
    };
    auto storeA = [&](int ch) {
        const int h0 = ch * 64;
#pragma unroll
        for (int pr = 0; pr < 2; pr++) {
            int row = pr * 64 + rl;
            __half2 nrp = pr ? nrp1 : nrp0;
#pragma unroll
            for (int g = 0; g < 2; g++) {
                uint4 wf = pf[pr * 2 + g];
                int h4 = g * 32 + 4 * s;
                __half2 G0 = *(const __half2*)(smem + SM_G + (h0 + h4) * 2);
                __half2 G1 = *(const __half2*)(smem + SM_G + (h0 + h4 + 2) * 2);
                __half2 u0 = __hfma2(nrp, u32_h2(wf.y), __hadd2(G0, u32_h2(wf.x)));
                __half2 u1 = __hfma2(nrp, u32_h2(wf.w), __hadd2(G1, u32_h2(wf.z)));
                uint2 hv;
                hv.x = h2_u32(__hmax2(u0, zero2));
                hv.y = h2_u32(__hmax2(u1, zero2));
                *(uint2*)(smem + SM_A + (ch & 1) * A_STRIDE +
                          SWZ(row * 128 + h4 * 2)) = hv;
            }
        }
    };

    // ldmatrix address precompute
    uint32_t aOff[2]; int aX[2];
#pragma unroll
    for (int mt = 0; mt < 2; mt++) {
        int rowA = rowg * 32 + mt * 16 + (lane & 15);
        aOff[mt] = rowA * 128;
        aX[mt]   = (rowA & 7) << 4;
    }
    const int aCol = lane & 16;
    int bRow[4], bX[4];
#pragma unroll
    for (int bt = 0; bt < 4; bt++) {
        int rowB = colg * 64 + bt * 16 + (lane & 7) + ((lane & 16) >> 1);
        bRow[bt] = rowB * 128;
        bX[bt]   = (rowB & 7) << 4;
    }
    const int bCol = (lane & 8) << 1;

    float D[2][8][4];
#pragma unroll
    for (int mt = 0; mt < 2; mt++)
#pragma unroll
        for (int nt = 0; nt < 8; nt++)
#pragma unroll
            for (int j = 0; j < 4; j++) D[mt][nt][j] = 0.f;

    // prologue: B0, B1 in flight; A0 built
    loadB(0);
    loadB(1);
    prefetchA(0);
    storeA(0);
    CP_WAIT1();                      // B0 complete (B1 may still fly)
    __syncthreads();

#pragma unroll 1
    for (int ch = 0; ch < 8; ch++) {
        if (ch < 6) loadB(ch + 2);           // into buffer (ch+2)%3 (freed last sync)
        if (ch < 7) prefetchA(ch + 1);
        const uint32_t bufA = sb + SM_A + (ch & 1) * A_STRIDE;
        const uint32_t bufB = sb + SM_B + (ch % 3) * B_STRIDE;
        // ---- MMA(ch): 4 k-steps of 16 ----
#pragma unroll
        for (int ks = 0; ks < 4; ks++) {
            const int cA = ks * 32 + aCol;
            const int cB = ks * 32 + bCol;
            uint32_t ah[2][4];
            ldsm_x4(ah[0], bufA + aOff[0] + (cA ^ aX[0]));
            ldsm_x4(ah[1], bufA + aOff[1] + (cA ^ aX[1]));
#pragma unroll
            for (int bth = 0; bth < 2; bth++) {
                uint32_t bh[2][4];
#pragma unroll
                for (int bb = 0; bb < 2; bb++) {
                    int bt = 2 * bth + bb;
                    ldsm_x4(bh[bb], bufB + bRow[bt] + (cB ^ bX[bt]));
                }
#pragma unroll
                for (int mt = 0; mt < 2; mt++)
#pragma unroll
                    for (int bb = 0; bb < 2; bb++) {
                        int nt = 4 * bth + 2 * bb;
                        mma_f16(D[mt][nt],     ah[mt], bh[bb]);
                        mma_f16(D[mt][nt + 1], ah[mt], bh[bb] + 2);
                    }
            }
        }
        if (ch < 7) storeA(ch + 1);          // other A buffer; no race with readers
        if (ch < 6) { CP_WAIT1(); }          // B(ch+1) done; B(ch+2) may still fly
        else        { CP_WAIT0(); }
        __syncthreads();
    }

    // ---- epilogue: BN2 + relu + W3 dot, reduce over o ----
#pragma unroll
    for (int mt = 0; mt < 2; mt++) {
        int r = rowg * 32 + mt * 16 + (lane >> 2);
        float s0 = 0.f, s1 = 0.f;
#pragma unroll
        for (int nt = 0; nt < 8; nt++) {
#pragma unroll
            for (int j = 0; j < 2; j++) {
                int o = colg * 64 + nt * 8 + 2 * (lane & 3) + j;
                float e1 = *(const float*)(smem + SM_E1 + o * 4);
                float e0 = *(const float*)(smem + SM_E0 + o * 4);
                float w3 = *(const float*)(smem + SM_W3 + o * 4);
                s0 = fmaf(fmaxf(fmaf(D[mt][nt][j],     e1, e0), 0.f), w3, s0);
                s1 = fmaf(fmaxf(fmaf(D[mt][nt][2 + j], e1, e0), 0.f), w3, s1);
            }
        }
        s0 += __shfl_xor_sync(0xffffffffu, s0, 1);
        s0 += __shfl_xor_sync(0xffffffffu, s0, 2);
        s1 += __shfl_xor_sync(0xffffffffu, s1, 1);
        s1 += __shfl_xor_sync(0xffffffffu, s1, 2);
        if ((lane & 3) == 0) {
            *(float*)(smem + SM_PART + (colg * 128 + r) * 4)     = s0;
            *(float*)(smem + SM_PART + (colg * 128 + r + 8) * 4) = s1;
        }
    }
    __syncthreads();
    if (t < 128) {
        float v = *(const float*)(smem + SM_PART + t * 4)
                + *(const float*)(smem + SM_PART + (128 + t) * 4)
                + *(const float*)(smem + SM_PART + (256 + t) * 4)
                + *(const float*)(smem + SM_PART + (384 + t) * 4);
        out[(size_t)b * ND + k0 + t] = v + b3[0];
    }
}

extern "C" void kernel_launch(void* const* d_in, const int* in_sizes, int n_in,
                              void* d_out, int out_size) {
    const float* rep   = (const float*)d_in[0];
    const float* emb   = (const float*)d_in[1];
    const float* W1    = (const float*)d_in[2];
    const float* b1    = (const float*)d_in[3];
    const float* g1    = (const float*)d_in[4];
    const float* beta1 = (const float*)d_in[5];
    const float* m1    = (const float*)d_in[6];
    const float* v1    = (const float*)d_in[7];
    const float* W2    = (const float*)d_in[8];
    const float* b2    = (const float*)d_in[9];
    const float* g2    = (const float*)d_in[10];
    const float* beta2 = (const float*)d_in[11];
    const float* m2    = (const float*)d_in[12];
    const float* v2    = (const float*)d_in[13];
    const float* W3    = (const float*)d_in[14];
    const float* b3    = (const float*)d_in[15];
    float* out = (float*)d_out;

    cudaFuncSetAttribute(fused_mma, cudaFuncAttributeMaxDynamicSharedMemorySize, SM_TOTAL);

    mega_prep<<<512, 512>>>(rep, emb, W1, W2, g1, v1);
    dim3 grid(ND / 128, NB);
    fused_mma<<<grid, 512, SM_TOTAL>>>(rep, b1, g1, beta1, m1, v1,
                                       b2, g2, beta2, m2, v2, W3, b3, out);
}